// round 17
// baseline (speedup 1.0000x reference)
#include <cuda_runtime.h>
#include <cuda_bf16.h>
#include <math.h>

// ---------------- scratch (bf16x2 complex intermediates) ----------------
__device__ __align__(16) unsigned g_s2h[8388608];  // [4][64][32][8][128] complexes (bf16 re,im)
__device__ __align__(16) float  g_W[8192];
__device__ __align__(16) float  g_Bias[512];
__device__ __align__(16) uint4  g_A4H[1024];       // bf16 fragments: [fwd-W M32K64: 512 | inv-W M64K32: 512]
__device__ __align__(16) uint4  g_A4L[64];         // inv-L: M=32(t), K=16(2l+pp), x2 + 1/sqrt32 baked
__device__ __align__(16) uint4  g_A4Lf[64];        // fwd-L: M=16(2l+pp), K=32(t), 1/sqrt32 baked

__device__ __forceinline__ float gelu_f(float v){
  return 0.5f*v*(1.0f+erff(v*0.7071067811865476f));
}
__device__ __forceinline__ unsigned bf2(float a, float b){
  __nv_bfloat162 h = __floats2bfloat162_rn(a, b);
  return *reinterpret_cast<unsigned*>(&h);
}
__device__ __forceinline__ float2 unbf2(unsigned u){
  __nv_bfloat162 h = *reinterpret_cast<__nv_bfloat162*>(&u);
  return __bfloat1622float2(h);
}
__device__ __forceinline__ void mma16(float4& d, uint4 a, unsigned b0, unsigned b1){
  asm volatile("mma.sync.aligned.m16n8k16.row.col.f32.bf16.bf16.f32 "
    "{%0,%1,%2,%3}, {%4,%5,%6,%7}, {%8,%9}, {%0,%1,%2,%3};"
    : "+f"(d.x), "+f"(d.y), "+f"(d.z), "+f"(d.w)
    : "r"(a.x), "r"(a.y), "r"(a.z), "r"(a.w), "r"(b0), "r"(b1));
}

// ---------------- K0a: bf16 m16n8k16 twiddle fragments ----------------
__global__ void k_init4h(){
  int j = blockIdx.x*256 + threadIdx.x;   // 0..1279 (guarded)
  int lane = j&31, qid = lane>>2, rid = lane&3;
  const double s32 = 0.17677669529663688911;
  if (j < 1024){
    int which = j>>9, t = j&511;
    int mat, kk16, mt;
    if (which==0){ mt=(t>>5)&1; kk16=(t>>6)&3; mat=t>>8; }   // fwd-W: M=32,K=64
    else         { mt=(t>>5)&3; kk16=(t>>7)&1; mat=t>>8; }   // inv-W: M=64,K=32
    int r0 = mt*16+qid, r1 = r0+8, k0 = kk16*16 + 2*rid;
    float v[8];
#pragma unroll
    for (int q=0; q<8; q++){
      int m = (q&1) ? r1 : r0;
      int k = k0 + (q>>2)*8 + ((q>>1)&1);
      double a = (double)(m*k)/32.0;
      v[q] = (float)((mat ? sinpi(a) : cospi(a))*0.125);
    }
    g_A4H[j] = make_uint4(bf2(v[0],v[2]), bf2(v[1],v[3]), bf2(v[4],v[6]), bf2(v[5],v[7]));
  } else if (j < 1088){
    int t = j-1024;                 // inv-L: rows = time t (M=32), K=16 (2l+pp)
    int mt = t>>5;
    int r0 = mt*16+qid, r1 = r0+8;
    float v[8];
#pragma unroll
    for (int q=0; q<8; q++){
      int m = (q&1) ? r1 : r0;
      int k = 2*rid + (q>>2)*8 + ((q>>1)&1);
      int l = k>>1, pp = k&1;
      double cl = (l==0)?1.0:2.0;
      double a = (double)(m*l)/16.0;
      v[q] = (float)((pp==0 ? cl*cospi(a) : -cl*sinpi(a))*s32);
    }
    g_A4L[t] = make_uint4(bf2(v[0],v[2]), bf2(v[1],v[3]), bf2(v[4],v[6]), bf2(v[5],v[7]));
  } else if (j < 1152){
    int t = j-1088;                 // fwd-L: rows = 2l+pp (M=16), K=32 (time t)
    int kk16 = t>>5;
    float v[8];
#pragma unroll
    for (int q=0; q<8; q++){
      int m = (q&1) ? qid+8 : qid;  // output row 2l+pp
      int l = m>>1, pp = m&1;
      int kt = kk16*16 + 2*rid + (q>>2)*8 + ((q>>1)&1);
      double a = (double)(kt*l)/16.0;
      v[q] = (float)((pp==0 ? cospi(a) : -sinpi(a))*s32);
    }
    g_A4Lf[t] = make_uint4(bf2(v[0],v[2]), bf2(v[1],v[3]), bf2(v[4],v[6]), bf2(v[5],v[7]));
  }
}

// ---------------- K0: fold HydraLoRA ----------------
__global__ void k_prep(const float* __restrict__ w1, const float* __restrict__ b1,
                       const float* __restrict__ w2, const float* __restrict__ b2,
                       const float* __restrict__ A1r, const float* __restrict__ B1r,
                       const float* __restrict__ A1i, const float* __restrict__ B1i,
                       const float* __restrict__ A2r, const float* __restrict__ B2r,
                       const float* __restrict__ A2i, const float* __restrict__ B2i,
                       const float* __restrict__ ew){
  int k  = blockIdx.x;
  int io = threadIdx.x;
  int i = io >> 4, o = io & 15;
  float e0 = ew[0], e1 = ew[1], e2 = ew[2], e3 = ew[3];
  const float s = 0.03125f;
  const float* Ws[4] = { w1 + k*256, w1 + 2048 + k*256, w2 + k*256, w2 + 2048 + k*256 };
  const float* As[4] = { A1r + k*512, A1i + k*512, A2r + k*512, A2i + k*512 };
  const float* Bs[4] = { B1r + k*2048, B1i + k*2048, B2r + k*2048, B2i + k*2048 };
#pragma unroll
  for (int m = 0; m < 4; m++){
    const float* A  = As[m] + i*32;
    const float* Bb = Bs[m];
    float acc = 0.f;
    for (int r = 0; r < 32; r++){
      float bm = e0*Bb[r*16+o] + e1*Bb[512+r*16+o] + e2*Bb[1024+r*16+o] + e3*Bb[1536+r*16+o];
      acc = fmaf(A[r], bm, acc);
    }
    g_W[((m*8+k)*16+i)*16+o] = Ws[m][i*16+o] + s*acc;
  }
  if (io < 16){
    float b10 = b1[k*16+io], b11 = b1[128+k*16+io];
    float b20 = b2[k*16+io], b21 = b2[128+k*16+io];
    g_Bias[      k*16+io] = b10 - b11;
    g_Bias[128 + k*16+io] = b10 + b11;
    g_Bias[256 + k*16+io] = b20 - b21;
    g_Bias[384 + k*16+io] = b20 + b21;
  }
}

// ---------------- K1: fused forward (fwd-L GEMM + fwd-W GEMM) ----------------
// grid (ct=16, y=64, b=4), 256 thr. S: B1 16x520 | B2 32x136 @0 | Es 32x68 @4352
__global__ void __launch_bounds__(256,3) k_fwd(const float* __restrict__ x){
  __shared__ __align__(16) unsigned S[8320];
  int tid = threadIdx.x;
  int ct = blockIdx.x, y = blockIdx.y, b = blockIdx.z;
  const float* xb = x + (size_t)(b*64+y)*262144 + ct*8;
  // stage B1: t-paired bf16, k2 = t>>1, n = xx*8 + c
  for (int i=tid; i<4096; i+=256){
    int cp = i&3, k2 = (i>>2)&15, xx = i>>6;
    float2 a  = *(const float2*)(xb + (size_t)xx*4096 + (2*k2)*128 + cp*2);
    float2 bb = *(const float2*)(xb + (size_t)xx*4096 + (2*k2+1)*128 + cp*2);
    *(uint2*)(S + k2*520 + xx*8 + cp*2) = make_uint2(bf2(a.x,bb.x), bf2(a.y,bb.y));
  }
  __syncthreads();
  int warp=tid>>5, lane=tid&31, qid=lane>>2, rid=lane&3;
  // GEMM1 fwd-L: M=16 (2l+pp), K=32 (t), N=512 (xx*8+c)
  float4 C1[8];
#pragma unroll
  for (int n=0;n<8;n++) C1[n] = make_float4(0.f,0.f,0.f,0.f);
#pragma unroll
  for (int kk=0; kk<2; kk++){
    int s0 = (kk*8+rid)*520, s1 = (kk*8+rid+4)*520;
    uint4 a = __ldg(&g_A4Lf[kk*32+lane]);
#pragma unroll
    for (int nt=0; nt<8; nt++){
      unsigned b0 = S[s0 + warp*64 + nt*8 + qid];
      unsigned b1 = S[s1 + warp*64 + nt*8 + qid];
      mma16(C1[nt], a, b0, b1);
    }
  }
  __syncthreads();
  // scatter -> B2: word(k2=xx>>1, n2=2*(l*8+c)+pp) = (val@xx even, val@xx odd)
  {
    int n2a = 16*(qid>>1) + 4*rid + (qid&1);
#pragma unroll
    for (int j=0; j<4; j++){
      int k2 = warp*4 + j;
      unsigned* d = S + k2*136;
      d[n2a]      = bf2(C1[2*j].x, C1[2*j+1].x);
      d[n2a+2]    = bf2(C1[2*j].y, C1[2*j+1].y);
      d[n2a+64]   = bf2(C1[2*j].z, C1[2*j+1].z);
      d[n2a+66]   = bf2(C1[2*j].w, C1[2*j+1].w);
    }
  }
  __syncthreads();
  // GEMM2 fwd-W: M=32 (w), K=64 (xx), N=128
  float4 C[2][2][2];
#pragma unroll
  for (int a=0;a<2;a++)
#pragma unroll
    for (int m=0;m<2;m++)
#pragma unroll
      for (int n=0;n<2;n++) C[a][m][n] = make_float4(0.f,0.f,0.f,0.f);
#pragma unroll
  for (int kk=0; kk<4; kk++){
    int s0 = (kk*8+rid)*136, s1 = (kk*8+rid+4)*136;
    unsigned b0n0 = S[s0 + warp*16 + qid];
    unsigned b1n0 = S[s1 + warp*16 + qid];
    unsigned b0n1 = S[s0 + warp*16 + 8 + qid];
    unsigned b1n1 = S[s1 + warp*16 + 8 + qid];
#pragma unroll
    for (int mat=0; mat<2; mat++){
#pragma unroll
      for (int mt=0; mt<2; mt++){
        uint4 af = __ldg(&g_A4H[((mat*4+kk)*2+mt)*32 + lane]);
        mma16(C[mat][mt][0], af, b0n0, b1n0);
        mma16(C[mat][mt][1], af, b0n1, b1n1);
      }
    }
  }
  // combine (fwd signs) -> Es (stride 68) at S+4352 (disjoint from B2 reads)
  unsigned* Es = S + 4352;
#pragma unroll
  for (int mt=0; mt<2; mt++)
#pragma unroll
    for (int nt=0; nt<2; nt++){
      float4 cr = C[0][mt][nt], ci = C[1][mt][nt];
      int colC = warp*8 + nt*4 + rid;
      int m0 = mt*16 + qid;
      Es[m0*68 + colC]     = bf2(cr.x + ci.y, cr.y - ci.x);
      Es[(m0+8)*68 + colC] = bf2(cr.z + ci.w, cr.w - ci.z);
    }
  __syncthreads();
  // coalesced write: g_s2h[b][y][w][l][ct*8..+8]
  {
    int ww = tid>>3, ll = tid&7;
    unsigned* og = g_s2h + (size_t)b*2097152 + (size_t)y*32768 + ww*1024 + ll*128 + ct*8;
    uint4 v0 = *(const uint4*)(Es + ww*68 + ll*8);
    uint4 v1 = *(const uint4*)(Es + ww*68 + ll*8 + 4);
    *(uint4*)og       = v0;
    *(uint4*)(og + 4) = v1;
  }
}

// ---------------- K_mid: fwd-H + MLP + inv-H in place (unchanged) ----------------
__global__ void __launch_bounds__(256,3) k_mid(){
  extern __shared__ float sm[];
  float* sW    = sm;
  float* sBias = sm + 4096;
  unsigned* U  = (unsigned*)(sm + 4368);
  unsigned* U2 = (unsigned*)(sm + 8720);
  int tid = threadIdx.x;
  int bx = blockIdx.x, b = blockIdx.y;
  int w = bx>>4, l = (bx>>1)&7, chalf = bx&1;
  for (int i=tid; i<1024; i+=256){
    int mg=i>>8, nb0=(i>>6)&3;
    ((float4*)sW)[i] = ((const float4*)g_W)[(mg*8+chalf*4+nb0)*64 + (i&63)];
  }
  { int mg=tid>>6, nb0=(tid>>4)&3, o=tid&15;
    sBias[(mg*4+nb0)*17+o] = g_Bias[mg*128 + (chalf*4+nb0)*16 + o]; }
  unsigned* gs = g_s2h + (size_t)b*2097152 + (size_t)w*1024 + l*128 + chalf*64;
  for (int i=tid; i<1024; i+=256){
    int k2 = i>>5, j2p = i&31;
    uint2 a = *(const uint2*)(gs + (size_t)(2*k2)*32768 + 2*j2p);
    uint2 bb = *(const uint2*)(gs + (size_t)(2*k2+1)*32768 + 2*j2p);
    *(uint4*)(U + k2*136 + 4*j2p) = make_uint4(
      __byte_perm(a.x, bb.x, 0x5410), __byte_perm(a.x, bb.x, 0x7632),
      __byte_perm(a.y, bb.y, 0x5410), __byte_perm(a.y, bb.y, 0x7632));
  }
  __syncthreads();
  int warp=tid>>5, lane=tid&31, qid=lane>>2, rid=lane&3;
  int wcol = warp*16;
  float4 C1[2][2][2];
#pragma unroll
  for (int a=0;a<2;a++)
#pragma unroll
    for (int m=0;m<2;m++)
#pragma unroll
      for (int n=0;n<2;n++) C1[a][m][n] = make_float4(0.f,0.f,0.f,0.f);
#pragma unroll
  for (int kk=0; kk<4; kk++){
    int s0 = (kk*8+rid)*136, s1 = (kk*8+rid+4)*136;
    unsigned b0n0 = U[s0 + wcol + qid];
    unsigned b1n0 = U[s1 + wcol + qid];
    unsigned b0n1 = U[s0 + wcol + 8 + qid];
    unsigned b1n1 = U[s1 + wcol + 8 + qid];
#pragma unroll
    for (int mat=0; mat<2; mat++){
#pragma unroll
      for (int mt=0; mt<2; mt++){
        uint4 af = __ldg(&g_A4H[((mat*4+kk)*2+mt)*32 + lane]);
        mma16(C1[mat][mt][0], af, b0n0, b1n0);
        mma16(C1[mat][mt][1], af, b0n1, b1n1);
      }
    }
  }
  __syncthreads();
  float2* sSpec = (float2*)U;
#pragma unroll
  for (int mt=0; mt<2; mt++)
#pragma unroll
    for (int nt=0; nt<2; nt++){
      float4 cc = C1[0][mt][nt], cs = C1[1][mt][nt];
      int c2 = warp*8+nt*4+rid, h0 = mt*16+qid;
      sSpec[h0*65 + c2]     = make_float2(cc.x+cs.y, cc.y-cs.x);
      sSpec[(h0+8)*65 + c2] = make_float2(cc.z+cs.w, cc.w-cs.z);
    }
  __syncthreads();
  {
    int inst=tid>>1, half=tid&1, nb0=inst>>5, h=inst&31;
    const float* W1R = sW + nb0*256;
    const float* W1I = sW + (4+nb0)*256;
    const float* W2R = sW + (8+nb0)*256;
    const float* W2I = sW + (12+nb0)*256;
    const float* Bb0 = sBias + nb0*17;
    const float* Bb1 = sBias + (4+nb0)*17;
    const float* Bb2 = sBias + (8+nb0)*17;
    const float* Bb3 = sBias + (12+nb0)*17;
    float2* myx = sSpec + h*65 + nb0*16;
    float xr[16], xi[16];
#pragma unroll
    for (int i=0;i<16;i++){ float2 v = myx[i]; xr[i]=v.x; xi[i]=v.y; }
    __syncthreads();
    float pr[8], pi[8];
#pragma unroll
    for (int oo=0;oo<8;oo++){ int o=half*8+oo; pr[oo]=Bb0[o]; pi[oo]=Bb1[o]; }
#pragma unroll
    for (int i=0;i<16;i++){
      float xrv = xr[i], xiv = xi[i];
#pragma unroll
      for (int o4=0;o4<2;o4++){
        float4 wr = *(const float4*)(W1R + i*16 + half*8 + o4*4);
        float4 wi = *(const float4*)(W1I + i*16 + half*8 + o4*4);
        pr[o4*4+0] += xrv*wr.x - xiv*wi.x;  pi[o4*4+0] += xiv*wr.x + xrv*wi.x;
        pr[o4*4+1] += xrv*wr.y - xiv*wi.y;  pi[o4*4+1] += xiv*wr.y + xrv*wi.y;
        pr[o4*4+2] += xrv*wr.z - xiv*wi.z;  pi[o4*4+2] += xiv*wr.z + xrv*wi.z;
        pr[o4*4+3] += xrv*wr.w - xiv*wi.w;  pi[o4*4+3] += xiv*wr.w + xrv*wi.w;
      }
    }
#pragma unroll
    for (int oo=0;oo<8;oo++){ pr[oo]=gelu_f(pr[oo]); pi[oo]=gelu_f(pi[oo]); }
#pragma unroll
    for (int oo=0;oo<8;oo++) myx[half*8+oo] = make_float2(pr[oo], pi[oo]);
    __syncthreads();
    float qr[8], qi[8];
#pragma unroll
    for (int oo=0;oo<8;oo++){ int o=half*8+oo; qr[oo]=Bb2[o]; qi[oo]=Bb3[o]; }
#pragma unroll
    for (int i=0;i<16;i++){
      float2 p = myx[i];
#pragma unroll
      for (int o4=0;o4<2;o4++){
        float4 wr = *(const float4*)(W2R + i*16 + half*8 + o4*4);
        float4 wi = *(const float4*)(W2I + i*16 + half*8 + o4*4);
        qr[o4*4+0] += p.x*wr.x - p.y*wi.x;  qi[o4*4+0] += p.y*wr.x + p.x*wi.x;
        qr[o4*4+1] += p.x*wr.y - p.y*wi.y;  qi[o4*4+1] += p.y*wr.y + p.x*wi.y;
        qr[o4*4+2] += p.x*wr.z - p.y*wi.z;  qi[o4*4+2] += p.y*wr.z + p.x*wi.z;
        qr[o4*4+3] += p.x*wr.w - p.y*wi.w;  qi[o4*4+3] += p.y*wr.w + p.x*wi.w;
      }
    }
    __nv_bfloat16* d16 = (__nv_bfloat16*)U2;
    int base = ((h>>1)*136)*2 + (h&1);
#pragma unroll
    for (int oo=0;oo<8;oo++){
      int n_re = 2*(nb0*16 + half*8 + oo);
      d16[base + n_re*2]     = __float2bfloat16_rn(qr[oo]);
      d16[base + (n_re+1)*2] = __float2bfloat16_rn(qi[oo]);
    }
  }
  __syncthreads();
  float4 C3[2][4][2];
#pragma unroll
  for (int a=0;a<2;a++)
#pragma unroll
    for (int m=0;m<4;m++)
#pragma unroll
      for (int n=0;n<2;n++) C3[a][m][n] = make_float4(0.f,0.f,0.f,0.f);
#pragma unroll
  for (int kk=0; kk<2; kk++){
    int s0 = (kk*8+rid)*136, s1 = (kk*8+rid+4)*136;
    unsigned b0n0 = U2[s0 + wcol + qid];
    unsigned b1n0 = U2[s1 + wcol + qid];
    unsigned b0n1 = U2[s0 + wcol + 8 + qid];
    unsigned b1n1 = U2[s1 + wcol + 8 + qid];
#pragma unroll
    for (int mat=0; mat<2; mat++){
#pragma unroll
      for (int mt=0; mt<4; mt++){
        uint4 af = __ldg(&g_A4H[512 + ((mat*2+kk)*4+mt)*32 + lane]);
        mma16(C3[mat][mt][0], af, b0n0, b1n0);
        mma16(C3[mat][mt][1], af, b0n1, b1n1);
      }
    }
  }
#pragma unroll
  for (int mt=0; mt<4; mt++)
#pragma unroll
    for (int nt=0; nt<2; nt++){
      float4 cc = C3[0][mt][nt], cs = C3[1][mt][nt];
      int c2 = warp*8+nt*4+rid, y0 = mt*16+qid;
      U[y0*68 + c2]     = bf2(cc.x-cs.y, cc.y+cs.x);
      U[(y0+8)*68 + c2] = bf2(cc.z-cs.w, cc.w+cs.z);
    }
  __syncthreads();
  {
    int r = tid>>2, sg = tid&3;
#pragma unroll
    for (int q=0; q<4; q++){
      uint4 v = *(const uint4*)(U + r*68 + sg*16 + q*4);
      *(uint4*)(gs + (size_t)r*32768 + sg*16 + q*4) = v;
    }
  }
}

// ---------------- K3: fused inverse (inv-W GEMM + inv-L GEMM + residual) ----------------
__global__ void __launch_bounds__(256,3) k_inv(const float* __restrict__ xin, float* __restrict__ out){
  __shared__ __align__(16) unsigned B1[2176];
  __shared__ __align__(16) unsigned B2[4160];
  int tid = threadIdx.x;
  int ct = blockIdx.x, y = blockIdx.y, b = blockIdx.z;
  const unsigned* gs = g_s2h + (size_t)b*2097152 + (size_t)y*32768 + ct*8;
  for (int i=tid; i<512; i+=256){
    int k2 = i>>5, l = (i>>2)&7, ccp = i&3;
    uint2 a  = *(const uint2*)(gs + (size_t)(2*k2)*1024 + l*128 + 2*ccp);
    uint2 bb = *(const uint2*)(gs + (size_t)(2*k2+1)*1024 + l*128 + 2*ccp);
    *(uint4*)(B1 + k2*136 + l*16 + 4*ccp) = make_uint4(
      __byte_perm(a.x, bb.x, 0x5410), __byte_perm(a.x, bb.x, 0x7632),
      __byte_perm(a.y, bb.y, 0x5410), __byte_perm(a.y, bb.y, 0x7632));
  }
  __syncthreads();
  int warp=tid>>5, lane=tid&31, qid=lane>>2, rid=lane&3;
  int wcol = warp*16;
  float4 C1[2][4][2];
#pragma unroll
  for (int a=0;a<2;a++)
#pragma unroll
    for (int m=0;m<4;m++)
#pragma unroll
      for (int n=0;n<2;n++) C1[a][m][n] = make_float4(0.f,0.f,0.f,0.f);
#pragma unroll
  for (int kk=0; kk<2; kk++){
    int s0 = (kk*8+rid)*136, s1 = (kk*8+rid+4)*136;
    unsigned b0n0 = B1[s0 + wcol + qid];
    unsigned b1n0 = B1[s1 + wcol + qid];
    unsigned b0n1 = B1[s0 + wcol + 8 + qid];
    unsigned b1n1 = B1[s1 + wcol + 8 + qid];
#pragma unroll
    for (int mat=0; mat<2; mat++){
#pragma unroll
      for (int mt=0; mt<4; mt++){
        uint4 af = __ldg(&g_A4H[512 + ((mat*2+kk)*4+mt)*32 + lane]);
        mma16(C1[mat][mt][0], af, b0n0, b1n0);
        mma16(C1[mat][mt][1], af, b0n1, b1n1);
      }
    }
  }
#pragma unroll
  for (int mt=0; mt<4; mt++)
#pragma unroll
    for (int nt=0; nt<2; nt++){
      float4 cc4 = C1[0][mt][nt], cs = C1[1][mt][nt];
      int colC = warp*8 + nt*4 + rid;
      int l = colC>>3, cc = colC&7;
      int xx0 = mt*16 + qid;
      B2[l*520 + xx0*8 + cc]     = bf2(cc4.x - cs.y, cc4.y + cs.x);
      B2[l*520 + (xx0+8)*8 + cc] = bf2(cc4.z - cs.w, cc4.w + cs.z);
    }
  __syncthreads();
  float4 C2[2][8];
#pragma unroll
  for (int m=0;m<2;m++)
#pragma unroll
    for (int n=0;n<8;n++) C2[m][n] = make_float4(0.f,0.f,0.f,0.f);
  {
    int s0 = rid*520, s1 = (rid+4)*520;
    uint4 a0 = __ldg(&g_A4L[lane]);
    uint4 a1 = __ldg(&g_A4L[32+lane]);
#pragma unroll
    for (int nt=0; nt<8; nt++){
      unsigned b0 = B2[s0 + warp*64 + nt*8 + qid];
      unsigned b1 = B2[s1 + warp*64 + nt*8 + qid];
      mma16(C2[0][nt], a0, b0, b1);
      mma16(C2[1][nt], a1, b0, b1);
    }
  }
  const float* xb = xin + (size_t)(b*64+y)*262144 + ct*8;
  float* ob = out + (size_t)(b*64+y)*262144 + ct*8;
#pragma unroll
  for (int mt=0; mt<2; mt++)
#pragma unroll
    for (int nt=0; nt<8; nt++){
      float4 cv = C2[mt][nt];
      int n = warp*64 + nt*8 + rid*2;
      int xx = n>>3, cc = n&7;
      int t0 = mt*16 + qid;
      size_t a0 = (size_t)xx*4096 + t0*128 + cc;
      size_t a1 = (size_t)xx*4096 + (t0+8)*128 + cc;
      float2 r0 = *(const float2*)(xb + a0);
      float2 r1 = *(const float2*)(xb + a1);
      *(float2*)(ob + a0) = make_float2(cv.x + r0.x, cv.y + r0.y);
      *(float2*)(ob + a1) = make_float2(cv.z + r1.x, cv.w + r1.y);
    }
}

// ---------------- launch ----------------
extern "C" void kernel_launch(void* const* d_in, const int* in_sizes, int n_in,
                              void* d_out, int out_size){
  (void)in_sizes; (void)n_in; (void)out_size;
  const float* x = (const float*)d_in[0];
  cudaFuncSetAttribute(k_mid, cudaFuncAttributeMaxDynamicSharedMemorySize, 43584);

  k_prep<<<8,256>>>((const float*)d_in[1], (const float*)d_in[2], (const float*)d_in[3],
                    (const float*)d_in[4], (const float*)d_in[5], (const float*)d_in[6],
                    (const float*)d_in[7], (const float*)d_in[8], (const float*)d_in[9],
                    (const float*)d_in[10], (const float*)d_in[11], (const float*)d_in[12],
                    (const float*)d_in[13]);
  k_init4h<<<5,256>>>();
  // fused fwd L + fwd W -> g_s2h
  k_fwd<<<dim3(16,64,4),256>>>(x);
  // fwd H + MLP + inv H, in place on g_s2h
  k_mid<<<dim3(512,4),256,43584>>>();
  // fused inv W + inv L + residual
  k_inv<<<dim3(16,64,4),256>>>(x, (float*)d_out);
}